// round 13
// baseline (speedup 1.0000x reference)
#include <cuda_runtime.h>
#include <cuda_pipeline.h>

#define BB 65536
#define VV 4
#define BPB 16                        // batches per block
#define THREADS 128                   // 2 threads per (batch,view) task
#define NBLK (BB / BPB)               // 4096

// shared layout in float4 units
#define IK4   0                       // transposed ik: 8 slots x stride 129
#define KW4   1032                    // 16 batches x stride 25 (24 data + 1 pad)
#define CAM4  1432                    // 16 x 12, unpadded (read via LDS.128)
#define KK4   1624                    // 16 x 10 (9 data + 1 pad)
#define SMEM_F4 1784
#define SMEM_BYTES (SMEM_F4 * 16)     // 28544

__device__ float g_partials[NBLK];
__device__ unsigned int g_ticket;

static __device__ __forceinline__ float warp_sum(float v) {
#pragma unroll
    for (int o = 16; o; o >>= 1) v += __shfl_xor_sync(0xFFFFFFFFu, v, o);
    return v;
}

__global__ __launch_bounds__(THREADS, 7) void proj_loss(
    const float* __restrict__ Kmat,   // (B,V,3,3)
    const float* __restrict__ cam,    // (B,V,3,4)
    const float* __restrict__ kw,     // (B,J,3)
    const float* __restrict__ ik,     // (B,V,J,2)
    float* __restrict__ out)
{
    extern __shared__ __align__(16) float4 sm4[];
    const float* smf = (const float*)sm4;
    __shared__ float s_w[4];
    __shared__ int s_last;

    const int tid = threadIdx.x;
    const int b0 = blockIdx.x * BPB;

    // ---------------- staging via cp.async (no regs, L1 bypass) ----------------
    {   // ik FIRST: 1024 f4 -> transposed [slot s][dest-thread]
        const float4* g = (const float4*)(ik + (size_t)b0 * 256);
#pragma unroll
        for (int r = 0; r < 8; ++r) {
            int i = tid + r * 128;
            int task = i >> 4, rem = i & 15;
            int hh = rem >> 3, s = rem & 7;
            __pipeline_memcpy_async(&sm4[IK4 + s * 129 + 2 * task + hh], &g[i], 16);
        }
    }
    {   // kw: 384 f4 -> rows stride 25
        const float4* g = (const float4*)(kw + (size_t)b0 * 96);
#pragma unroll
        for (int r = 0; r < 3; ++r) {
            int i = tid + r * 128, b = i / 24, k = i - b * 24;
            __pipeline_memcpy_async(&sm4[KW4 + b * 25 + k], &g[i], 16);
        }
    }
    {   // cam: 192 f4, unpadded 1:1
        const float4* g = (const float4*)(cam + (size_t)b0 * 48);
#pragma unroll
        for (int r = 0; r < 2; ++r) {
            int i = tid + r * 128;
            if (i < 192)
                __pipeline_memcpy_async(&sm4[CAM4 + i], &g[i], 16);
        }
    }
    {   // K: 144 f4 -> rows stride 10 (16B-aligned dst)
        const float4* g = (const float4*)(Kmat + (size_t)b0 * 36);
#pragma unroll
        for (int r = 0; r < 2; ++r) {
            int i = tid + r * 128;
            if (i < 144) {
                int b = i / 9, k = i - b * 9;
                __pipeline_memcpy_async(&sm4[KK4 + b * 10 + k], &g[i], 16);
            }
        }
    }
    __pipeline_commit();
    __pipeline_wait_prior(0);
    __syncthreads();

    // ------------- mapping: 2 threads per task, 16 joints each -------------
    const int h  = tid & 1;           // half (joints 16h .. 16h+15)
    const int v  = (tid >> 1) & 3;    // view
    const int bl = tid >> 3;          // local batch

    // ---- ni2 first: independent 8 LDS.128 in flight early ----
    float ni2 = 0.f;
#pragma unroll
    for (int s = 0; s < 8; ++s) {
        float4 q = sm4[IK4 + s * 129 + tid];
        ni2 = fmaf(q.x, q.x, fmaf(q.y, q.y, ni2));
        ni2 = fmaf(q.z, q.z, fmaf(q.w, q.w, ni2));
    }

    // camera rows as 3 f4; K scalars at conflict-free stride 40
    const int cb = CAM4 + bl * 12 + v * 3;
    const float4 cv0 = sm4[cb];       // R00 R01 R02 t0
    const float4 cv1 = sm4[cb + 1];   // R10 R11 R12 t1
    const float4 cv2 = sm4[cb + 2];   // R20 R21 R22 t2
    const float* kp = smf + KK4 * 4 + bl * 40 + v * 9;
    const float K00 = kp[0], K01 = kp[1], c0 = kp[2];
    const float K10 = kp[3], K11 = kp[4], c1 = kp[5];

    // folded rows: num = A.X + d ; u = num*izb + c
    const float A00 = fmaf(K00, cv0.x, K01 * cv1.x);
    const float A01 = fmaf(K00, cv0.y, K01 * cv1.y);
    const float A02 = fmaf(K00, cv0.z, K01 * cv1.z);
    const float d0  = fmaf(K00, cv0.w, K01 * cv1.w);
    const float A10 = fmaf(K10, cv0.x, K11 * cv1.x);
    const float A11 = fmaf(K10, cv0.y, K11 * cv1.y);
    const float A12 = fmaf(K10, cv0.z, K11 * cv1.z);
    const float d1  = fmaf(K10, cv0.w, K11 * cv1.w);

    // ---- single pass over X: numerators (regs) + norm partials + z partial ----
    const int xb = KW4 + bl * 25 + 12 * h;   // this half's 12 f4 of X
    float2 uv[16];
    float Szp = 0.f, Snn = 0.f, Snx = 0.f, Sny = 0.f;
#pragma unroll
    for (int g = 0; g < 4; ++g) {
        float4 p0 = sm4[xb + g * 3];
        float4 p1 = sm4[xb + g * 3 + 1];
        float4 p2 = sm4[xb + g * 3 + 2];
        float xs[4] = {p0.x, p0.w, p1.z, p2.y};
        float ys[4] = {p0.y, p1.x, p1.w, p2.z};
        float zs[4] = {p0.z, p1.y, p2.x, p2.w};
#pragma unroll
        for (int j = 0; j < 4; ++j) {
            int jj = g * 4 + j;
            float nx = fmaf(A00, xs[j], fmaf(A01, ys[j], fmaf(A02, zs[j], d0)));
            float ny = fmaf(A10, xs[j], fmaf(A11, ys[j], fmaf(A12, zs[j], d1)));
            uv[jj] = make_float2(nx, ny);
            Snn = fmaf(nx, nx, fmaf(ny, ny, Snn));
            Snx += nx; Sny += ny;
            Szp = fmaf(cv2.x, xs[j], fmaf(cv2.y, ys[j], fmaf(cv2.z, zs[j], Szp)));
        }
    }
    Szp += __shfl_xor_sync(0xFFFFFFFFu, Szp, 1);
    const float zbar = Szp * (1.0f / 32.0f) + cv2.w;
    const float izb  = __fdividef(1.0f, zbar);

    // closed-form half-norm of projected points
    float np2 = fmaf(izb * izb, Snn,
                fmaf(2.0f * izb, fmaf(c0, Snx, c1 * Sny),
                     16.0f * fmaf(c0, c0, c1 * c1)));

    np2 += __shfl_xor_sync(0xFFFFFFFFu, np2, 1);
    ni2 += __shfl_xor_sync(0xFFFFFFFFu, ni2, 1);
    const float rp = rsqrtf(np2);
    const float ri = rsqrtf(ni2);
    const float f  = izb * rp;
    const float e0 = c0 * rp;
    const float e1 = c1 * rp;

    // ---- diff pass: |num*f + e - q*ri| , re-read ik from smem ----
    float acc = 0.f;
#pragma unroll
    for (int s = 0; s < 8; ++s) {
        float4 q = sm4[IK4 + s * 129 + tid];
        acc += fabsf(fmaf(uv[2*s].x,   f, fmaf(-q.x, ri, e0)))
             + fabsf(fmaf(uv[2*s].y,   f, fmaf(-q.y, ri, e1)))
             + fabsf(fmaf(uv[2*s+1].x, f, fmaf(-q.z, ri, e0)))
             + fabsf(fmaf(uv[2*s+1].y, f, fmaf(-q.w, ri, e1)));
    }

    // ---------------- block partial + last-block deterministic reduce --------
    acc = warp_sum(acc);
    if ((tid & 31) == 0) s_w[tid >> 5] = acc;
    __syncthreads();
    if (tid == 0) {
        float bsum = s_w[0] + s_w[1] + s_w[2] + s_w[3];
        __stcg(&g_partials[blockIdx.x], bsum);
        __threadfence();
        unsigned int t = atomicAdd(&g_ticket, 1u);
        s_last = (t == NBLK - 1u);
    }
    __syncthreads();

    if (s_last) {
        float a = 0.f;
#pragma unroll
        for (int i = 0; i < NBLK / THREADS; ++i)
            a += __ldcg(&g_partials[tid * (NBLK / THREADS) + i]);
        a = warp_sum(a);
        if ((tid & 31) == 0) s_w[tid >> 5] = a;
        __syncthreads();
        if (tid == 0) {
            float tot = s_w[0] + s_w[1] + s_w[2] + s_w[3];
            out[0] = tot * (1.0f / (64.0f * (float)BB * (float)VV));
            g_ticket = 0u;
        }
    }
}

extern "C" void kernel_launch(void* const* d_in, const int* in_sizes, int n_in,
                              void* d_out, int out_size)
{
    const float* Kmat = (const float*)d_in[0];  // (B,V,3,3)
    const float* cam  = (const float*)d_in[1];  // (B,V,3,4)
    const float* kw   = (const float*)d_in[2];  // (B,J,3)
    const float* ik   = (const float*)d_in[3];  // (B,V,J,2)
    float* out = (float*)d_out;

    cudaFuncSetAttribute(proj_loss, cudaFuncAttributeMaxDynamicSharedMemorySize, SMEM_BYTES);
    proj_loss<<<NBLK, THREADS, SMEM_BYTES>>>(Kmat, cam, kw, ik, out);
}

// round 14
// speedup vs baseline: 1.1885x; 1.1885x over previous
#include <cuda_runtime.h>

#define BB 65536
#define VV 4
#define BPB 16                        // batches per block
#define THREADS 128                   // 2 threads per (batch,view) task
#define NBLK (BB / BPB)               // 4096

// shared layout, f4 units unless noted
#define KW4   0                       // 16 batches x stride 25 f4 (24 data + 1 pad)
#define IK4   400                     // transposed: 8 slots x stride 129 f4
#define CAMF  5728                    // floats: 16 x stride 49 (48 data + 1 pad)
#define KKF   6512                    // floats: 16 x stride 37 (36 data + 1 pad)
#define SMEM_FLOATS 7104
#define SMEM_BYTES (SMEM_FLOATS * 4)  // 28416

__device__ float g_partials[NBLK];
__device__ unsigned int g_ticket;

static __device__ __forceinline__ float warp_sum(float v) {
#pragma unroll
    for (int o = 16; o; o >>= 1) v += __shfl_xor_sync(0xFFFFFFFFu, v, o);
    return v;
}

__global__ __launch_bounds__(THREADS, 7) void proj_loss(
    const float* __restrict__ Kmat,   // (B,V,3,3)
    const float* __restrict__ cam,    // (B,V,3,4)
    const float* __restrict__ kw,     // (B,J,3)
    const float* __restrict__ ik,     // (B,V,J,2)
    float* __restrict__ out)
{
    extern __shared__ float sm[];
    float4* sm4 = (float4*)sm;
    __shared__ float s_w[4];
    __shared__ int s_last;

    const int tid = threadIdx.x;
    const int b0 = blockIdx.x * BPB;

    // ------------------------- staging (proven LDG layout) -------------------------
    {   // kw: 16*24 = 384 f4
        const float4* g = (const float4*)(kw + (size_t)b0 * 96);
#pragma unroll
        for (int r = 0; r < 3; ++r) {
            int i = tid + r * 128, b = i / 24, k = i - b * 24;
            sm4[KW4 + b * 25 + k] = __ldcg(&g[i]);
        }
    }
    {   // ik: 1024 f4 -> transposed [slot s][dest-thread]
        const float4* g = (const float4*)(ik + (size_t)b0 * 256);
#pragma unroll
        for (int r = 0; r < 8; ++r) {
            int i = tid + r * 128;
            int task = i >> 4, rem = i & 15;
            int hh = rem >> 3, s = rem & 7;
            sm4[IK4 + s * 129 + 2 * task + hh] = __ldcg(&g[i]);
        }
    }
    {   // cam: 192 f4 -> scalar scatter, odd stride
        const float4* g = (const float4*)(cam + (size_t)b0 * 48);
#pragma unroll
        for (int r = 0; r < 2; ++r) {
            int i = tid + r * 128;
            if (i < 192) {
                int b = i / 12, k = i - b * 12;
                float4 val = __ldcg(&g[i]);
                int base = CAMF + b * 49 + k * 4;
                sm[base] = val.x; sm[base + 1] = val.y;
                sm[base + 2] = val.z; sm[base + 3] = val.w;
            }
        }
    }
    {   // K: 144 f4
        const float4* g = (const float4*)(Kmat + (size_t)b0 * 36);
#pragma unroll
        for (int r = 0; r < 2; ++r) {
            int i = tid + r * 128;
            if (i < 144) {
                int b = i / 9, k = i - b * 9;
                float4 val = __ldcg(&g[i]);
                int base = KKF + b * 37 + k * 4;
                sm[base] = val.x; sm[base + 1] = val.y;
                sm[base + 2] = val.z; sm[base + 3] = val.w;
            }
        }
    }
    __syncthreads();

    // ------------- mapping: 2 threads per task, 16 joints each -------------
    const int h  = tid & 1;           // half (joints 16h .. 16h+15)
    const int v  = (tid >> 1) & 3;    // view
    const int bl = tid >> 3;          // local batch

    // ---- ni2 first: independent 8 LDS.128 in flight early ----
    float ni2 = 0.f;
#pragma unroll
    for (int s = 0; s < 8; ++s) {
        float4 q = sm4[IK4 + s * 129 + tid];
        ni2 = fmaf(q.x, q.x, fmaf(q.y, q.y, ni2));
        ni2 = fmaf(q.z, q.z, fmaf(q.w, q.w, ni2));
    }

    const float* cv = &sm[CAMF + bl * 49 + v * 12];
    const float R00=cv[0], R01=cv[1], R02=cv[2],  t0=cv[3];
    const float R10=cv[4], R11=cv[5], R12=cv[6],  t1=cv[7];
    const float R20=cv[8], R21=cv[9], R22=cv[10], t2=cv[11];
    const float* kp = &sm[KKF + bl * 37 + v * 9];
    const float K00=kp[0], K01=kp[1], c0=kp[2];
    const float K10=kp[3], K11=kp[4], c1=kp[5];

    // folded rows: num = A.X + d ; u = num*izb + c
    const float A00 = fmaf(K00, R00, K01 * R10);
    const float A01 = fmaf(K00, R01, K01 * R11);
    const float A02 = fmaf(K00, R02, K01 * R12);
    const float d0  = fmaf(K00, t0,  K01 * t1);
    const float A10 = fmaf(K10, R00, K11 * R10);
    const float A11 = fmaf(K10, R01, K11 * R11);
    const float A12 = fmaf(K10, R02, K11 * R12);
    const float d1  = fmaf(K10, t0,  K11 * t1);

    // ---- single pass over X: numerators (regs) + norm partials + z partial ----
    const int xb = KW4 + bl * 25 + 12 * h;   // this half's 12 f4 of X
    float2 uv[16];
    float Szp = 0.f, Snn = 0.f, Snx = 0.f, Sny = 0.f;
#pragma unroll
    for (int g = 0; g < 4; ++g) {
        float4 p0 = sm4[xb + g * 3];
        float4 p1 = sm4[xb + g * 3 + 1];
        float4 p2 = sm4[xb + g * 3 + 2];
        float xs[4] = {p0.x, p0.w, p1.z, p2.y};
        float ys[4] = {p0.y, p1.x, p1.w, p2.z};
        float zs[4] = {p0.z, p1.y, p2.x, p2.w};
#pragma unroll
        for (int j = 0; j < 4; ++j) {
            int jj = g * 4 + j;
            float nx = fmaf(A00, xs[j], fmaf(A01, ys[j], fmaf(A02, zs[j], d0)));
            float ny = fmaf(A10, xs[j], fmaf(A11, ys[j], fmaf(A12, zs[j], d1)));
            uv[jj] = make_float2(nx, ny);
            Snn = fmaf(nx, nx, fmaf(ny, ny, Snn));
            Snx += nx; Sny += ny;
            Szp = fmaf(R20, xs[j], fmaf(R21, ys[j], fmaf(R22, zs[j], Szp)));
        }
    }
    Szp += __shfl_xor_sync(0xFFFFFFFFu, Szp, 1);
    const float zbar = Szp * (1.0f / 32.0f) + t2;
    const float izb  = __fdividef(1.0f, zbar);

    // closed-form half-norm of projected points
    float np2 = fmaf(izb * izb, Snn,
                fmaf(2.0f * izb, fmaf(c0, Snx, c1 * Sny),
                     16.0f * fmaf(c0, c0, c1 * c1)));

    np2 += __shfl_xor_sync(0xFFFFFFFFu, np2, 1);
    ni2 += __shfl_xor_sync(0xFFFFFFFFu, ni2, 1);
    const float rp = rsqrtf(np2);
    const float ri = rsqrtf(ni2);
    const float f  = izb * rp;
    const float e0 = c0 * rp;
    const float e1 = c1 * rp;

    // ---- diff pass: |num*f + e - q*ri| , re-read ik from smem ----
    float acc = 0.f;
#pragma unroll
    for (int s = 0; s < 8; ++s) {
        float4 q = sm4[IK4 + s * 129 + tid];
        acc += fabsf(fmaf(uv[2*s].x,   f, fmaf(-q.x, ri, e0)))
             + fabsf(fmaf(uv[2*s].y,   f, fmaf(-q.y, ri, e1)))
             + fabsf(fmaf(uv[2*s+1].x, f, fmaf(-q.z, ri, e0)))
             + fabsf(fmaf(uv[2*s+1].y, f, fmaf(-q.w, ri, e1)));
    }

    // ---------------- block partial + last-block deterministic reduce --------
    acc = warp_sum(acc);
    if ((tid & 31) == 0) s_w[tid >> 5] = acc;
    __syncthreads();
    if (tid == 0) {
        float bsum = s_w[0] + s_w[1] + s_w[2] + s_w[3];
        __stcg(&g_partials[blockIdx.x], bsum);
        __threadfence();
        unsigned int t = atomicAdd(&g_ticket, 1u);
        s_last = (t == NBLK - 1u);
    }
    __syncthreads();

    if (s_last) {
        float a = 0.f;
#pragma unroll
        for (int i = 0; i < NBLK / THREADS; ++i)
            a += __ldcg(&g_partials[tid * (NBLK / THREADS) + i]);
        a = warp_sum(a);
        if ((tid & 31) == 0) s_w[tid >> 5] = a;
        __syncthreads();
        if (tid == 0) {
            float tot = s_w[0] + s_w[1] + s_w[2] + s_w[3];
            out[0] = tot * (1.0f / (64.0f * (float)BB * (float)VV));
            g_ticket = 0u;
        }
    }
}

extern "C" void kernel_launch(void* const* d_in, const int* in_sizes, int n_in,
                              void* d_out, int out_size)
{
    const float* Kmat = (const float*)d_in[0];  // (B,V,3,3)
    const float* cam  = (const float*)d_in[1];  // (B,V,3,4)
    const float* kw   = (const float*)d_in[2];  // (B,J,3)
    const float* ik   = (const float*)d_in[3];  // (B,V,J,2)
    float* out = (float*)d_out;

    cudaFuncSetAttribute(proj_loss, cudaFuncAttributeMaxDynamicSharedMemorySize, SMEM_BYTES);
    proj_loss<<<NBLK, THREADS, SMEM_BYTES>>>(Kmat, cam, kw, ik, out);
}

// round 15
// speedup vs baseline: 1.2546x; 1.0557x over previous
#include <cuda_runtime.h>

#define BB 65536
#define VV 4
#define BPB 16                        // batches per block
#define THREADS 128                   // 2 threads per (batch,view) task
#define NBLK (BB / BPB)               // 4096

// shared layout, f4 units unless noted
#define KW4   0                       // 16 batches x stride 25 f4 (24 data + 1 pad)
#define IK4   400                     // transposed: 8 slots x stride 129 f4
#define CAMF  5728                    // floats: 16 x stride 49 (48 data + 1 pad)
#define KKF   6512                    // floats: 16 x stride 37 (36 data + 1 pad)
#define SMEM_FLOATS 7104
#define SMEM_BYTES (SMEM_FLOATS * 4)  // 28416

__device__ float g_partials[NBLK];
__device__ unsigned int g_ticket;

static __device__ __forceinline__ float warp_sum(float v) {
#pragma unroll
    for (int o = 16; o; o >>= 1) v += __shfl_xor_sync(0xFFFFFFFFu, v, o);
    return v;
}

__global__ __launch_bounds__(THREADS, 5) void proj_loss(
    const float* __restrict__ Kmat,   // (B,V,3,3)
    const float* __restrict__ cam,    // (B,V,3,4)
    const float* __restrict__ kw,     // (B,J,3)
    const float* __restrict__ ik,     // (B,V,J,2)
    float* __restrict__ out)
{
    extern __shared__ float sm[];
    float4* sm4 = (float4*)sm;
    __shared__ float s_w[4];
    __shared__ int s_last;

    const int tid = threadIdx.x;
    const int b0 = blockIdx.x * BPB;

    // ---- phase 1a: issue ik loads FIRST, hold in regs (STS deferred) ----
    float4 ikreg[8];
    {
        const float4* g = (const float4*)(ik + (size_t)b0 * 256);
#pragma unroll
        for (int r = 0; r < 8; ++r)
            ikreg[r] = __ldcg(&g[tid + r * 128]);
    }

    // ---- phase 1b: stage kw/cam/K (27% of bytes) ----
    {   // kw: 16*24 = 384 f4
        const float4* g = (const float4*)(kw + (size_t)b0 * 96);
#pragma unroll
        for (int r = 0; r < 3; ++r) {
            int i = tid + r * 128, b = i / 24, k = i - b * 24;
            sm4[KW4 + b * 25 + k] = __ldcg(&g[i]);
        }
    }
    {   // cam: 192 f4 -> scalar scatter, odd stride
        const float4* g = (const float4*)(cam + (size_t)b0 * 48);
#pragma unroll
        for (int r = 0; r < 2; ++r) {
            int i = tid + r * 128;
            if (i < 192) {
                int b = i / 12, k = i - b * 12;
                float4 val = __ldcg(&g[i]);
                int base = CAMF + b * 49 + k * 4;
                sm[base] = val.x; sm[base + 1] = val.y;
                sm[base + 2] = val.z; sm[base + 3] = val.w;
            }
        }
    }
    {   // K: 144 f4
        const float4* g = (const float4*)(Kmat + (size_t)b0 * 36);
#pragma unroll
        for (int r = 0; r < 2; ++r) {
            int i = tid + r * 128;
            if (i < 144) {
                int b = i / 9, k = i - b * 9;
                float4 val = __ldcg(&g[i]);
                int base = KKF + b * 37 + k * 4;
                sm[base] = val.x; sm[base + 1] = val.y;
                sm[base + 2] = val.z; sm[base + 3] = val.w;
            }
        }
    }
    __syncthreads();   // kw/cam/K visible; ik LDGs still in flight

    // ------------- mapping: 2 threads per task, 16 joints each -------------
    const int h  = tid & 1;           // half (joints 16h .. 16h+15)
    const int v  = (tid >> 1) & 3;    // view
    const int bl = tid >> 3;          // local batch

    const float* cv = &sm[CAMF + bl * 49 + v * 12];
    const float R00=cv[0], R01=cv[1], R02=cv[2],  t0=cv[3];
    const float R10=cv[4], R11=cv[5], R12=cv[6],  t1=cv[7];
    const float R20=cv[8], R21=cv[9], R22=cv[10], t2=cv[11];
    const float* kp = &sm[KKF + bl * 37 + v * 9];
    const float K00=kp[0], K01=kp[1], c0=kp[2];
    const float K10=kp[3], K11=kp[4], c1=kp[5];

    // folded rows: num = A.X + d ; u = num*izb + c
    const float A00 = fmaf(K00, R00, K01 * R10);
    const float A01 = fmaf(K00, R01, K01 * R11);
    const float A02 = fmaf(K00, R02, K01 * R12);
    const float d0  = fmaf(K00, t0,  K01 * t1);
    const float A10 = fmaf(K10, R00, K11 * R10);
    const float A11 = fmaf(K10, R01, K11 * R11);
    const float A12 = fmaf(K10, R02, K11 * R12);
    const float d1  = fmaf(K10, t0,  K11 * t1);

    // ---- phase 2: X pass under the shadow of ik loads ----
    const int xb = KW4 + bl * 25 + 12 * h;   // this half's 12 f4 of X
    float2 uv[16];
    float Szp = 0.f, Snn = 0.f, Snx = 0.f, Sny = 0.f;
#pragma unroll
    for (int g = 0; g < 4; ++g) {
        float4 p0 = sm4[xb + g * 3];
        float4 p1 = sm4[xb + g * 3 + 1];
        float4 p2 = sm4[xb + g * 3 + 2];
        float xs[4] = {p0.x, p0.w, p1.z, p2.y};
        float ys[4] = {p0.y, p1.x, p1.w, p2.z};
        float zs[4] = {p0.z, p1.y, p2.x, p2.w};
#pragma unroll
        for (int j = 0; j < 4; ++j) {
            int jj = g * 4 + j;
            float nx = fmaf(A00, xs[j], fmaf(A01, ys[j], fmaf(A02, zs[j], d0)));
            float ny = fmaf(A10, xs[j], fmaf(A11, ys[j], fmaf(A12, zs[j], d1)));
            uv[jj] = make_float2(nx, ny);
            Snn = fmaf(nx, nx, fmaf(ny, ny, Snn));
            Snx += nx; Sny += ny;
            Szp = fmaf(R20, xs[j], fmaf(R21, ys[j], fmaf(R22, zs[j], Szp)));
        }
    }
    Szp += __shfl_xor_sync(0xFFFFFFFFu, Szp, 1);
    const float zbar = Szp * (1.0f / 32.0f) + t2;
    const float izb  = __fdividef(1.0f, zbar);

    // closed-form half-norm of projected points
    float np2 = fmaf(izb * izb, Snn,
                fmaf(2.0f * izb, fmaf(c0, Snx, c1 * Sny),
                     16.0f * fmaf(c0, c0, c1 * c1)));

    // ---- phase 3: deferred ik STS (loads complete by now), transposed ----
#pragma unroll
    for (int r = 0; r < 8; ++r) {
        int i = tid + r * 128;
        int task = i >> 4, rem = i & 15;
        int hh = rem >> 3, s = rem & 7;
        sm4[IK4 + s * 129 + 2 * task + hh] = ikreg[r];
    }
    __syncthreads();

    // ---- phase 4: ni2 + diff from transposed smem ----
    float ni2 = 0.f;
#pragma unroll
    for (int s = 0; s < 8; ++s) {
        float4 q = sm4[IK4 + s * 129 + tid];
        ni2 = fmaf(q.x, q.x, fmaf(q.y, q.y, ni2));
        ni2 = fmaf(q.z, q.z, fmaf(q.w, q.w, ni2));
    }
    np2 += __shfl_xor_sync(0xFFFFFFFFu, np2, 1);
    ni2 += __shfl_xor_sync(0xFFFFFFFFu, ni2, 1);
    const float rp = rsqrtf(np2);
    const float ri = rsqrtf(ni2);
    const float f  = izb * rp;
    const float e0 = c0 * rp;
    const float e1 = c1 * rp;

    float acc = 0.f;
#pragma unroll
    for (int s = 0; s < 8; ++s) {
        float4 q = sm4[IK4 + s * 129 + tid];
        acc += fabsf(fmaf(uv[2*s].x,   f, fmaf(-q.x, ri, e0)))
             + fabsf(fmaf(uv[2*s].y,   f, fmaf(-q.y, ri, e1)))
             + fabsf(fmaf(uv[2*s+1].x, f, fmaf(-q.z, ri, e0)))
             + fabsf(fmaf(uv[2*s+1].y, f, fmaf(-q.w, ri, e1)));
    }

    // ---------------- block partial + last-block deterministic reduce --------
    acc = warp_sum(acc);
    if ((tid & 31) == 0) s_w[tid >> 5] = acc;
    __syncthreads();
    if (tid == 0) {
        float bsum = s_w[0] + s_w[1] + s_w[2] + s_w[3];
        __stcg(&g_partials[blockIdx.x], bsum);
        __threadfence();
        unsigned int t = atomicAdd(&g_ticket, 1u);
        s_last = (t == NBLK - 1u);
    }
    __syncthreads();

    if (s_last) {
        float a = 0.f;
#pragma unroll
        for (int i = 0; i < NBLK / THREADS; ++i)
            a += __ldcg(&g_partials[tid * (NBLK / THREADS) + i]);
        a = warp_sum(a);
        if ((tid & 31) == 0) s_w[tid >> 5] = a;
        __syncthreads();
        if (tid == 0) {
            float tot = s_w[0] + s_w[1] + s_w[2] + s_w[3];
            out[0] = tot * (1.0f / (64.0f * (float)BB * (float)VV));
            g_ticket = 0u;
        }
    }
}

extern "C" void kernel_launch(void* const* d_in, const int* in_sizes, int n_in,
                              void* d_out, int out_size)
{
    const float* Kmat = (const float*)d_in[0];  // (B,V,3,3)
    const float* cam  = (const float*)d_in[1];  // (B,V,3,4)
    const float* kw   = (const float*)d_in[2];  // (B,J,3)
    const float* ik   = (const float*)d_in[3];  // (B,V,J,2)
    float* out = (float*)d_out;

    cudaFuncSetAttribute(proj_loss, cudaFuncAttributeMaxDynamicSharedMemorySize, SMEM_BYTES);
    proj_loss<<<NBLK, THREADS, SMEM_BYTES>>>(Kmat, cam, kw, ik, out);
}

// round 16
// speedup vs baseline: 1.2677x; 1.0104x over previous
#include <cuda_runtime.h>

#define BB 65536
#define VV 4
#define BPB 16                        // batches per block
#define THREADS 128                   // 2 threads per (batch,view) task
#define NBLK (BB / BPB)               // 4096

// shared layout, f4 units unless noted
#define KW4   0                       // 16 batches x stride 25 f4 (24 data + 1 pad)
#define IK4   400                     // transposed: 8 slots x stride 129 f4
#define CAMF  5728                    // floats: 16 x stride 49 (48 data + 1 pad)
#define KKF   6512                    // floats: 16 x stride 37 (36 data + 1 pad)
#define SMEM_FLOATS 7104
#define SMEM_BYTES (SMEM_FLOATS * 4)  // 28416

__device__ float g_partials[NBLK];
__device__ unsigned int g_ticket;

static __device__ __forceinline__ float warp_sum(float v) {
#pragma unroll
    for (int o = 16; o; o >>= 1) v += __shfl_xor_sync(0xFFFFFFFFu, v, o);
    return v;
}

__global__ __launch_bounds__(THREADS, 6) void proj_loss(
    const float* __restrict__ Kmat,   // (B,V,3,3)
    const float* __restrict__ cam,    // (B,V,3,4)
    const float* __restrict__ kw,     // (B,J,3)
    const float* __restrict__ ik,     // (B,V,J,2)
    float* __restrict__ out)
{
    extern __shared__ float sm[];
    float4* sm4 = (float4*)sm;
    __shared__ float s_w[4];
    __shared__ int s_last;

    const int tid = threadIdx.x;
    const int b0 = blockIdx.x * BPB;

    // ---- phase 1a: FIRST in program order — half of ik into registers ----
    float4 ikreg[4];
    const float4* gik = (const float4*)(ik + (size_t)b0 * 256);
#pragma unroll
    for (int r = 0; r < 4; ++r)
        ikreg[r] = __ldcg(&gik[tid + r * 128]);

    // ---- phase 1b: second ik half direct to transposed smem ----
#pragma unroll
    for (int r = 4; r < 8; ++r) {
        int i = tid + r * 128;
        int task = i >> 4, rem = i & 15;
        int hh = rem >> 3, s = rem & 7;
        sm4[IK4 + s * 129 + 2 * task + hh] = __ldcg(&gik[i]);
    }

    // ---- phase 1c: kw/cam/K (proven layout) ----
    {   // kw: 16*24 = 384 f4
        const float4* g = (const float4*)(kw + (size_t)b0 * 96);
#pragma unroll
        for (int r = 0; r < 3; ++r) {
            int i = tid + r * 128, b = i / 24, k = i - b * 24;
            sm4[KW4 + b * 25 + k] = __ldcg(&g[i]);
        }
    }
    {   // cam: 192 f4 -> scalar scatter, odd stride
        const float4* g = (const float4*)(cam + (size_t)b0 * 48);
#pragma unroll
        for (int r = 0; r < 2; ++r) {
            int i = tid + r * 128;
            if (i < 192) {
                int b = i / 12, k = i - b * 12;
                float4 val = __ldcg(&g[i]);
                int base = CAMF + b * 49 + k * 4;
                sm[base] = val.x; sm[base + 1] = val.y;
                sm[base + 2] = val.z; sm[base + 3] = val.w;
            }
        }
    }
    {   // K: 144 f4
        const float4* g = (const float4*)(Kmat + (size_t)b0 * 36);
#pragma unroll
        for (int r = 0; r < 2; ++r) {
            int i = tid + r * 128;
            if (i < 144) {
                int b = i / 9, k = i - b * 9;
                float4 val = __ldcg(&g[i]);
                int base = KKF + b * 37 + k * 4;
                sm[base] = val.x; sm[base + 1] = val.y;
                sm[base + 2] = val.z; sm[base + 3] = val.w;
            }
        }
    }
    __syncthreads();   // kw/cam/K + ik-2nd-half visible; ikreg loads may still fly

    // ------------- mapping: 2 threads per task, 16 joints each -------------
    const int h  = tid & 1;           // half (joints 16h .. 16h+15)
    const int v  = (tid >> 1) & 3;    // view
    const int bl = tid >> 3;          // local batch

    const float* cv = &sm[CAMF + bl * 49 + v * 12];
    const float R00=cv[0], R01=cv[1], R02=cv[2],  t0=cv[3];
    const float R10=cv[4], R11=cv[5], R12=cv[6],  t1=cv[7];
    const float R20=cv[8], R21=cv[9], R22=cv[10], t2=cv[11];
    const float* kp = &sm[KKF + bl * 37 + v * 9];
    const float K00=kp[0], K01=kp[1], c0=kp[2];
    const float K10=kp[3], K11=kp[4], c1=kp[5];

    // folded rows: num = A.X + d ; u = num*izb + c
    const float A00 = fmaf(K00, R00, K01 * R10);
    const float A01 = fmaf(K00, R01, K01 * R11);
    const float A02 = fmaf(K00, R02, K01 * R12);
    const float d0  = fmaf(K00, t0,  K01 * t1);
    const float A10 = fmaf(K10, R00, K11 * R10);
    const float A11 = fmaf(K10, R01, K11 * R11);
    const float A12 = fmaf(K10, R02, K11 * R12);
    const float d1  = fmaf(K10, t0,  K11 * t1);

    // ---- phase 2: X pass (under the shadow of the ikreg loads) ----
    const int xb = KW4 + bl * 25 + 12 * h;   // this half's 12 f4 of X
    float2 uv[16];
    float Szp = 0.f, Snn = 0.f, Snx = 0.f, Sny = 0.f;
#pragma unroll
    for (int g = 0; g < 4; ++g) {
        float4 p0 = sm4[xb + g * 3];
        float4 p1 = sm4[xb + g * 3 + 1];
        float4 p2 = sm4[xb + g * 3 + 2];
        float xs[4] = {p0.x, p0.w, p1.z, p2.y};
        float ys[4] = {p0.y, p1.x, p1.w, p2.z};
        float zs[4] = {p0.z, p1.y, p2.x, p2.w};
#pragma unroll
        for (int j = 0; j < 4; ++j) {
            int jj = g * 4 + j;
            float nx = fmaf(A00, xs[j], fmaf(A01, ys[j], fmaf(A02, zs[j], d0)));
            float ny = fmaf(A10, xs[j], fmaf(A11, ys[j], fmaf(A12, zs[j], d1)));
            uv[jj] = make_float2(nx, ny);
            Snn = fmaf(nx, nx, fmaf(ny, ny, Snn));
            Snx += nx; Sny += ny;
            Szp = fmaf(R20, xs[j], fmaf(R21, ys[j], fmaf(R22, zs[j], Szp)));
        }
    }
    Szp += __shfl_xor_sync(0xFFFFFFFFu, Szp, 1);
    const float zbar = Szp * (1.0f / 32.0f) + t2;
    const float izb  = __fdividef(1.0f, zbar);

    // closed-form half-norm of projected points
    float np2 = fmaf(izb * izb, Snn,
                fmaf(2.0f * izb, fmaf(c0, Snx, c1 * Sny),
                     16.0f * fmaf(c0, c0, c1 * c1)));

    // ---- phase 3: deferred STS of the register-held ik half ----
#pragma unroll
    for (int r = 0; r < 4; ++r) {
        int i = tid + r * 128;
        int task = i >> 4, rem = i & 15;
        int hh = rem >> 3, s = rem & 7;
        sm4[IK4 + s * 129 + 2 * task + hh] = ikreg[r];
    }
    __syncthreads();

    // ---- phase 4: ni2 + diff from transposed smem ----
    float ni2 = 0.f;
#pragma unroll
    for (int s = 0; s < 8; ++s) {
        float4 q = sm4[IK4 + s * 129 + tid];
        ni2 = fmaf(q.x, q.x, fmaf(q.y, q.y, ni2));
        ni2 = fmaf(q.z, q.z, fmaf(q.w, q.w, ni2));
    }
    np2 += __shfl_xor_sync(0xFFFFFFFFu, np2, 1);
    ni2 += __shfl_xor_sync(0xFFFFFFFFu, ni2, 1);
    const float rp = rsqrtf(np2);
    const float ri = rsqrtf(ni2);
    const float f  = izb * rp;
    const float e0 = c0 * rp;
    const float e1 = c1 * rp;

    float acc = 0.f;
#pragma unroll
    for (int s = 0; s < 8; ++s) {
        float4 q = sm4[IK4 + s * 129 + tid];
        acc += fabsf(fmaf(uv[2*s].x,   f, fmaf(-q.x, ri, e0)))
             + fabsf(fmaf(uv[2*s].y,   f, fmaf(-q.y, ri, e1)))
             + fabsf(fmaf(uv[2*s+1].x, f, fmaf(-q.z, ri, e0)))
             + fabsf(fmaf(uv[2*s+1].y, f, fmaf(-q.w, ri, e1)));
    }

    // ---------------- block partial + last-block deterministic reduce --------
    acc = warp_sum(acc);
    if ((tid & 31) == 0) s_w[tid >> 5] = acc;
    __syncthreads();
    if (tid == 0) {
        float bsum = s_w[0] + s_w[1] + s_w[2] + s_w[3];
        __stcg(&g_partials[blockIdx.x], bsum);
        __threadfence();
        unsigned int t = atomicAdd(&g_ticket, 1u);
        s_last = (t == NBLK - 1u);
    }
    __syncthreads();

    if (s_last) {
        float a = 0.f;
#pragma unroll
        for (int i = 0; i < NBLK / THREADS; ++i)
            a += __ldcg(&g_partials[tid * (NBLK / THREADS) + i]);
        a = warp_sum(a);
        if ((tid & 31) == 0) s_w[tid >> 5] = a;
        __syncthreads();
        if (tid == 0) {
            float tot = s_w[0] + s_w[1] + s_w[2] + s_w[3];
            out[0] = tot * (1.0f / (64.0f * (float)BB * (float)VV));
            g_ticket = 0u;
        }
    }
}

extern "C" void kernel_launch(void* const* d_in, const int* in_sizes, int n_in,
                              void* d_out, int out_size)
{
    const float* Kmat = (const float*)d_in[0];  // (B,V,3,3)
    const float* cam  = (const float*)d_in[1];  // (B,V,3,4)
    const float* kw   = (const float*)d_in[2];  // (B,J,3)
    const float* ik   = (const float*)d_in[3];  // (B,V,J,2)
    float* out = (float*)d_out;

    cudaFuncSetAttribute(proj_loss, cudaFuncAttributeMaxDynamicSharedMemorySize, SMEM_BYTES);
    proj_loss<<<NBLK, THREADS, SMEM_BYTES>>>(Kmat, cam, kw, ik, out);
}